// round 13
// baseline (speedup 1.0000x reference)
#include <cuda_runtime.h>

// MSELoss: out = mean((yhat - y)^2) over 16384 x 4096 fp32.  FINAL (converged).
// Session-converged configuration — every lever measured across 12 rounds:
//  - 256-bit streaming loads, L1::evict_first.L2::evict_first
//    (sm_103a requires .v8.f32 for the L2 hint; policy worth ~+1% DRAM)
//  - grid=2368 = 148 SMs x 16 = exactly 2 full-occupancy residency waves
//    (swept 1/2/2.5/4 waves; integer-2 measured best)
//  - __launch_bounds__(256,8): regs pinned at 32, 8 blocks/SM resident
//    (36-reg slip previously cost 30% occupancy — guard is load-bearing)
//  - pointer-increment stream loop (no per-iter IMAD address chain)
//  - fused finalize: device scratch + last-block-done, single graph node
// Measured: 78.3us end-to-end, ~6.9 TB/s = 86-88% of HBM spec (chip's
// practical LTS streaming ceiling; path-independent per B300 microarch).

#define BLOCK 256
#define GRID  2368   // 148 * 16

__device__ float    g_sum   = 0.0f;
__device__ unsigned g_count = 0u;

__device__ __forceinline__ void ldg256_stream(const float* p,
                                              float& v0, float& v1, float& v2, float& v3,
                                              float& v4, float& v5, float& v6, float& v7) {
    asm volatile("ld.global.nc.L1::evict_first.L2::evict_first.v8.f32 "
                 "{%0,%1,%2,%3,%4,%5,%6,%7}, [%8];"
                 : "=f"(v0), "=f"(v1), "=f"(v2), "=f"(v3),
                   "=f"(v4), "=f"(v5), "=f"(v6), "=f"(v7)
                 : "l"(p));
}

__global__ void __launch_bounds__(BLOCK, 8)
mse_kernel(const float* __restrict__ yhat,
           const float* __restrict__ y,
           float* __restrict__ out,
           int n8, float inv_n) {
    float acc = 0.0f;
    const int tid0   = blockIdx.x * BLOCK + threadIdx.x;
    const int stride = GRID * BLOCK;               // in v8 units
    const size_t step = (size_t)stride * 8;        // floats per stride

    const float* pa = yhat + (size_t)tid0 * 8;
    const float* pb = y    + (size_t)tid0 * 8;

    for (int i = tid0; i < n8; i += stride, pa += step, pb += step) {
        float a0, a1, a2, a3, a4, a5, a6, a7;
        float b0, b1, b2, b3, b4, b5, b6, b7;
        ldg256_stream(pa, a0, a1, a2, a3, a4, a5, a6, a7);
        ldg256_stream(pb, b0, b1, b2, b3, b4, b5, b6, b7);
        float d;
        d = a0 - b0; acc = fmaf(d, d, acc);
        d = a1 - b1; acc = fmaf(d, d, acc);
        d = a2 - b2; acc = fmaf(d, d, acc);
        d = a3 - b3; acc = fmaf(d, d, acc);
        d = a4 - b4; acc = fmaf(d, d, acc);
        d = a5 - b5; acc = fmaf(d, d, acc);
        d = a6 - b6; acc = fmaf(d, d, acc);
        d = a7 - b7; acc = fmaf(d, d, acc);
    }

    // warp reduce
    #pragma unroll
    for (int off = 16; off > 0; off >>= 1)
        acc += __shfl_xor_sync(0xFFFFFFFFu, acc, off);

    __shared__ float warp_sums[BLOCK / 32];
    int lane = threadIdx.x & 31;
    int wid  = threadIdx.x >> 5;
    if (lane == 0) warp_sums[wid] = acc;
    __syncthreads();

    if (threadIdx.x == 0) {
        float bsum = 0.0f;
        #pragma unroll
        for (int w = 0; w < BLOCK / 32; w++) bsum += warp_sums[w];

        float prior = atomicAdd(&g_sum, bsum);
        __threadfence();
        unsigned t = atomicAdd(&g_count, 1u);
        if (t == GRID - 1) {
            out[0] = (prior + bsum) * inv_n;
            g_sum   = 0.0f;   // reset for next graph replay
            g_count = 0u;
        }
    }
}

extern "C" void kernel_launch(void* const* d_in, const int* in_sizes, int n_in,
                              void* d_out, int out_size) {
    const float* yhat = (const float*)d_in[0];
    const float* y    = (const float*)d_in[1];
    float* out = (float*)d_out;

    long long n = (long long)in_sizes[0];   // 67108864
    int n8 = (int)(n / 8);                  // 8388608 (16384*4096 % 8 == 0)
    float inv_n = 1.0f / (float)n;

    mse_kernel<<<GRID, BLOCK>>>(yhat, y, out, n8, inv_n);
}

// round 14
// speedup vs baseline: 1.0103x; 1.0103x over previous
#include <cuda_runtime.h>

// MSELoss: out = mean((yhat - y)^2) over 16384 x 4096 fp32.
// Converged config + final unswept axis: block shape.
//  - BLOCK=512, 4 blocks/SM (same 2048 thr/SM), grid=1184 = 148 x 8
//    = exactly 2 full-occupancy residency waves (measured-best structure);
//    halves per-block epilogues (block-reduces, atomics, barriers).
//  - 256-bit streaming loads, L1::evict_first.L2::evict_first
//  - __launch_bounds__(512,4): regs pinned <= 32
//  - pointer-increment stream loop
//  - fused finalize: device scratch + last-block-done, single graph node

#define BLOCK 512
#define GRID  1184   // 148 * 8 -> 2 waves at 4 resident blocks/SM

__device__ float    g_sum   = 0.0f;
__device__ unsigned g_count = 0u;

__device__ __forceinline__ void ldg256_stream(const float* p,
                                              float& v0, float& v1, float& v2, float& v3,
                                              float& v4, float& v5, float& v6, float& v7) {
    asm volatile("ld.global.nc.L1::evict_first.L2::evict_first.v8.f32 "
                 "{%0,%1,%2,%3,%4,%5,%6,%7}, [%8];"
                 : "=f"(v0), "=f"(v1), "=f"(v2), "=f"(v3),
                   "=f"(v4), "=f"(v5), "=f"(v6), "=f"(v7)
                 : "l"(p));
}

__global__ void __launch_bounds__(BLOCK, 4)
mse_kernel(const float* __restrict__ yhat,
           const float* __restrict__ y,
           float* __restrict__ out,
           int n8, float inv_n) {
    float acc = 0.0f;
    const int tid0   = blockIdx.x * BLOCK + threadIdx.x;
    const int stride = GRID * BLOCK;               // in v8 units (same 303104 total threads)
    const size_t step = (size_t)stride * 8;        // floats per stride

    const float* pa = yhat + (size_t)tid0 * 8;
    const float* pb = y    + (size_t)tid0 * 8;

    for (int i = tid0; i < n8; i += stride, pa += step, pb += step) {
        float a0, a1, a2, a3, a4, a5, a6, a7;
        float b0, b1, b2, b3, b4, b5, b6, b7;
        ldg256_stream(pa, a0, a1, a2, a3, a4, a5, a6, a7);
        ldg256_stream(pb, b0, b1, b2, b3, b4, b5, b6, b7);
        float d;
        d = a0 - b0; acc = fmaf(d, d, acc);
        d = a1 - b1; acc = fmaf(d, d, acc);
        d = a2 - b2; acc = fmaf(d, d, acc);
        d = a3 - b3; acc = fmaf(d, d, acc);
        d = a4 - b4; acc = fmaf(d, d, acc);
        d = a5 - b5; acc = fmaf(d, d, acc);
        d = a6 - b6; acc = fmaf(d, d, acc);
        d = a7 - b7; acc = fmaf(d, d, acc);
    }

    // warp reduce
    #pragma unroll
    for (int off = 16; off > 0; off >>= 1)
        acc += __shfl_xor_sync(0xFFFFFFFFu, acc, off);

    __shared__ float warp_sums[BLOCK / 32];
    int lane = threadIdx.x & 31;
    int wid  = threadIdx.x >> 5;
    if (lane == 0) warp_sums[wid] = acc;
    __syncthreads();

    if (threadIdx.x == 0) {
        float bsum = 0.0f;
        #pragma unroll
        for (int w = 0; w < BLOCK / 32; w++) bsum += warp_sums[w];

        float prior = atomicAdd(&g_sum, bsum);
        __threadfence();
        unsigned t = atomicAdd(&g_count, 1u);
        if (t == GRID - 1) {
            out[0] = (prior + bsum) * inv_n;
            g_sum   = 0.0f;   // reset for next graph replay
            g_count = 0u;
        }
    }
}

extern "C" void kernel_launch(void* const* d_in, const int* in_sizes, int n_in,
                              void* d_out, int out_size) {
    const float* yhat = (const float*)d_in[0];
    const float* y    = (const float*)d_in[1];
    float* out = (float*)d_out;

    long long n = (long long)in_sizes[0];   // 67108864
    int n8 = (int)(n / 8);                  // 8388608 (16384*4096 % 8 == 0)
    float inv_n = 1.0f / (float)n;

    mse_kernel<<<GRID, BLOCK>>>(yhat, y, out, n8, inv_n);
}